// round 3
// baseline (speedup 1.0000x reference)
#include <cuda_runtime.h>

#define BDIM 384
#define CDIM 512
#define B2 (BDIM * BDIM)   // 147456

// ---------------- scratch (no allocations allowed) ----------------
__device__ __align__(16) float d_Gs[B2];
__device__ __align__(16) float d_Gt[B2];
__device__ __align__(16) float d_Ds[B2];
__device__ __align__(16) float d_Dt[B2];
__device__ __align__(16) float d_iDs[B2];
__device__ __align__(16) float d_iDt[B2];
__device__ float d_sqA[2][BDIM];
__device__ double d_acc[5];   // 0:sumDs 1:sumDt 2:hardCE 3:dist 4:angle
__device__ int d_labmode;     // 1 = labels are int64, 0 = int32

// ---------------- helpers ----------------
__device__ __forceinline__ float block_reduce_256(float v) {
    __shared__ float sh[8];
    #pragma unroll
    for (int o = 16; o; o >>= 1) v += __shfl_xor_sync(0xffffffffu, v, o);
    int lane = threadIdx.x & 31, w = threadIdx.x >> 5;
    if (lane == 0) sh[w] = v;
    __syncthreads();
    if (w == 0) {
        v = (lane < (blockDim.x >> 5)) ? sh[lane] : 0.f;
        #pragma unroll
        for (int o = 4; o; o >>= 1) v += __shfl_xor_sync(0xffffffffu, v, o);
    }
    return v;  // valid on thread 0
}

// ---------------- K0: init accumulators + detect label width ----------------
__global__ void k_init(const int* __restrict__ lab32) {
    __shared__ int any_hi;
    int t = threadIdx.x;
    if (t < 5) d_acc[t] = 0.0;
    if (t == 0) any_hi = 0;
    __syncthreads();
    // If labels are int64 (values < 512), every odd int32 word is 0.
    for (int i = t; i < 192; i += blockDim.x)
        if (lab32[2 * i + 1] != 0) any_hi = 1;   // benign race, same value
    __syncthreads();
    if (t == 0) d_labmode = any_hi ? 0 : 1;
}

// ---------------- K1: G = F F^T  (tile 64x32, 128 threads, 4x4 micro) ----------------
__global__ void __launch_bounds__(128) k_gemm(const float* __restrict__ fs,
                                              const float* __restrict__ ft) {
    __shared__ float sI[64][33];
    __shared__ float sJ[32][33];
    const int z = blockIdx.z;
    const float* __restrict__ F = z ? ft : fs;
    float* __restrict__ G = z ? d_Gt : d_Gs;
    const int i0 = blockIdx.x * 64;
    const int j0 = blockIdx.y * 32;
    const int tid = threadIdx.x;
    const int tx = tid & 7, ty = tid >> 3;

    float acc[4][4] = {};
    for (int k0 = 0; k0 < CDIM; k0 += 32) {
        #pragma unroll
        for (int e = tid; e < 512; e += 128) {
            int r = e >> 3, k4 = (e & 7) << 2;
            float4 v = *(const float4*)(F + (i0 + r) * CDIM + k0 + k4);
            sI[r][k4 + 0] = v.x; sI[r][k4 + 1] = v.y;
            sI[r][k4 + 2] = v.z; sI[r][k4 + 3] = v.w;
        }
        #pragma unroll
        for (int e = tid; e < 256; e += 128) {
            int r = e >> 3, k4 = (e & 7) << 2;
            float4 v = *(const float4*)(F + (j0 + r) * CDIM + k0 + k4);
            sJ[r][k4 + 0] = v.x; sJ[r][k4 + 1] = v.y;
            sJ[r][k4 + 2] = v.z; sJ[r][k4 + 3] = v.w;
        }
        __syncthreads();
        #pragma unroll
        for (int kk = 0; kk < 32; kk++) {
            float av[4], bv[4];
            #pragma unroll
            for (int a = 0; a < 4; a++) av[a] = sI[ty * 4 + a][kk];
            #pragma unroll
            for (int c = 0; c < 4; c++) bv[c] = sJ[tx * 4 + c][kk];
            #pragma unroll
            for (int a = 0; a < 4; a++)
                #pragma unroll
                for (int c = 0; c < 4; c++)
                    acc[a][c] = fmaf(av[a], bv[c], acc[a][c]);
        }
        __syncthreads();
    }
    #pragma unroll
    for (int a = 0; a < 4; a++) {
        float4 v = make_float4(acc[a][0], acc[a][1], acc[a][2], acc[a][3]);
        *(float4*)(G + (i0 + ty * 4 + a) * BDIM + j0 + tx * 4) = v;
    }
}

// ---------------- K2: D, invD (diag forced 0), sum(D), capture sq=diag(G) ----------------
__global__ void k_pdist() {
    const int z = blockIdx.y;
    const float* __restrict__ G  = z ? d_Gt  : d_Gs;
    float* __restrict__ D  = z ? d_Dt  : d_Ds;
    float* __restrict__ iD = z ? d_iDt : d_iDs;
    float part = 0.f;
    for (int e = blockIdx.x * blockDim.x + threadIdx.x; e < B2;
         e += gridDim.x * blockDim.x) {
        int i = e / BDIM;
        int j = e - i * BDIM;
        float g = G[e];
        float d;
        if (i == j) {
            d = 0.f;
            iD[e] = 0.f;          // exact zero-vector handling for angle term
            d_sqA[z][i] = g;      // sq = diag(G), bit-identical to G[b,b]
        } else {
            float sqi = G[i * (BDIM + 1)];
            float sqj = G[j * (BDIM + 1)];
            d = sqrtf(fmaxf(sqi + sqj - 2.f * g, 1e-12f));
            iD[e] = 1.f / d;
        }
        D[e] = d;
        part += d;
    }
    part = block_reduce_256(part);
    if (threadIdx.x == 0) atomicAdd(&d_acc[z], (double)part);
}

// ---------------- K3: hard CE (one warp per row) ----------------
__global__ void k_ce(const float* __restrict__ fs, const int* __restrict__ lab32) {
    int r = blockIdx.x * 8 + (threadIdx.x >> 5);
    int lane = threadIdx.x & 31;
    const float* x = fs + r * CDIM;
    float m = -1e30f;
    for (int c = lane; c < CDIM; c += 32) m = fmaxf(m, x[c]);
    #pragma unroll
    for (int o = 16; o; o >>= 1) m = fmaxf(m, __shfl_xor_sync(0xffffffffu, m, o));
    float s = 0.f;
    for (int c = lane; c < CDIM; c += 32) s += expf(x[c] - m);
    #pragma unroll
    for (int o = 16; o; o >>= 1) s += __shfl_xor_sync(0xffffffffu, s, o);
    if (lane == 0) {
        int L = lab32[d_labmode ? 2 * r : r];
        float loss = (logf(s) + m) - x[L];
        atomicAdd(&d_acc[2], (double)loss);
    }
}

// ---------------- K4: dist smooth-L1 ----------------
__global__ void k_dist() {
    float ims = (float)(147072.0 / d_acc[0]);   // 1/mean_pos_s
    float imt = (float)(147072.0 / d_acc[1]);
    float part = 0.f;
    for (int e = blockIdx.x * blockDim.x + threadIdx.x; e < B2;
         e += gridDim.x * blockDim.x) {
        float a = fabsf(d_Ds[e] * ims - d_Dt[e] * imt);
        float mm = fminf(a, 1.f);
        part = fmaf(mm, fmaf(-0.5f, mm, a), part);   // smooth-L1 = m*(a - m/2)
    }
    part = block_reduce_256(part);
    if (threadIdx.x == 0) atomicAdd(&d_acc[3], (double)part);
}

// ---------------- K5: angle smooth-L1 over B^3 via Gram identity ----------------
// gram[b,i,j] = (G[i,j] - G[b,i] - G[b,j] + G[b,b]) * invD[b,i] * invD[b,j]
// (i,j) symmetry: tiles with tj>ti weighted 2x, diagonal tiles computed fully.
__global__ void __launch_bounds__(256) k_angle() {
    // decode (ti, tj) pair, tj >= ti, 6 tiles of 64 -> 21 pairs
    int rem = blockIdx.x, ti = 0;
    while (rem >= 6 - ti) { rem -= 6 - ti; ti++; }
    int tj = ti + rem;

    const int tid = threadIdx.x;
    const int tx = tid & 15, ty = tid >> 4;
    const int i0 = ti * 64 + ty * 4;
    const int j0 = tj * 64 + tx * 4;

    float gs[4][4], gt[4][4];
    #pragma unroll
    for (int a = 0; a < 4; a++) {
        float4 v = *(const float4*)(d_Gs + (i0 + a) * BDIM + j0);
        gs[a][0] = v.x; gs[a][1] = v.y; gs[a][2] = v.z; gs[a][3] = v.w;
        float4 w = *(const float4*)(d_Gt + (i0 + a) * BDIM + j0);
        gt[a][0] = w.x; gt[a][1] = w.y; gt[a][2] = w.z; gt[a][3] = w.w;
    }

    const int b0 = (blockIdx.y * BDIM) / 7;
    const int b1 = ((blockIdx.y + 1) * BDIM) / 7;

    float acc = 0.f;
    for (int b = b0; b < b1; b++) {
        const int ro = b * BDIM;
        float gbiS[4], gbjS[4], ibiS[4], ibjS[4];
        float gbiT[4], gbjT[4], ibiT[4], ibjT[4];
        *(float4*)gbiS = *(const float4*)(d_Gs  + ro + i0);
        *(float4*)gbjS = *(const float4*)(d_Gs  + ro + j0);
        *(float4*)ibiS = *(const float4*)(d_iDs + ro + i0);
        *(float4*)ibjS = *(const float4*)(d_iDs + ro + j0);
        *(float4*)gbiT = *(const float4*)(d_Gt  + ro + i0);
        *(float4*)gbjT = *(const float4*)(d_Gt  + ro + j0);
        *(float4*)ibiT = *(const float4*)(d_iDt + ro + i0);
        *(float4*)ibjT = *(const float4*)(d_iDt + ro + j0);
        float sqS = d_sqA[0][b], sqT = d_sqA[1][b];
        float piS[4], piT[4];
        #pragma unroll
        for (int a = 0; a < 4; a++) { piS[a] = sqS - gbiS[a]; piT[a] = sqT - gbiT[a]; }

        #pragma unroll
        for (int a = 0; a < 4; a++) {
            #pragma unroll
            for (int c = 0; c < 4; c++) {
                float vs = (gs[a][c] + piS[a] - gbjS[c]) * (ibiS[a] * ibjS[c]);
                float vt = (gt[a][c] + piT[a] - gbjT[c]) * (ibiT[a] * ibjT[c]);
                float ad = fabsf(vs - vt);
                float mm = fminf(ad, 1.f);
                acc = fmaf(mm, fmaf(-0.5f, mm, ad), acc);
            }
        }
    }
    if (ti != tj) acc *= 2.f;
    acc = block_reduce_256(acc);
    if (tid == 0) atomicAdd(&d_acc[4], (double)acc);
}

// ---------------- K6: finalize ----------------
__global__ void k_fin(float* __restrict__ out, int n) {
    for (int i = threadIdx.x; i < n; i += blockDim.x) {
        if (i == 0) {
            double tot = d_acc[2] / (double)BDIM          // hard CE mean
                       + d_acc[3] / (double)B2            // dist smooth-L1 mean
                       + d_acc[4] / ((double)BDIM * (double)B2); // angle mean over B^3
            out[0] = (float)tot;
        } else {
            out[i] = 0.f;
        }
    }
}

// ---------------- launch ----------------
extern "C" void kernel_launch(void* const* d_in, const int* in_sizes, int n_in,
                              void* d_out, int out_size) {
    const float* fs = (const float*)d_in[0];
    const float* ft = (const float*)d_in[1];
    const int*   lb = (const int*)d_in[2];   // width auto-detected (i32 vs i64)
    float* out = (float*)d_out;

    k_init<<<1, 256>>>(lb);
    k_gemm<<<dim3(6, 12, 2), 128>>>(fs, ft);
    k_pdist<<<dim3(144, 2), 256>>>();
    k_ce<<<48, 256>>>(fs, lb);
    k_dist<<<144, 256>>>();
    k_angle<<<dim3(21, 7), 256>>>();
    k_fin<<<1, 256>>>(out, out_size);
}

// round 4
// speedup vs baseline: 1.0027x; 1.0027x over previous
#include <cuda_runtime.h>

typedef unsigned long long u64;
#define BDIM 384
#define CDIM 512
#define B2   147456   // 384*384

// ---------------- scratch (no allocations allowed) ----------------
__device__ __align__(16) float d_Gs[B2];    // K-split part 0 (s), later combined G
__device__ __align__(16) float d_Gt[B2];
__device__ __align__(16) float d_G2s[B2];   // K-split part 1
__device__ __align__(16) float d_G2t[B2];
__device__ __align__(16) float d_iDs[B2];
__device__ __align__(16) float d_iDt[B2];
__device__ float d_dg[2][2][BDIM];          // diag partials [z][ksplit][i]
__device__ float d_sqA[2][BDIM];            // combined diag (sq norms)
__device__ float d_dsum[288];               // pdist partial sums [z*144 + blk]
__device__ float d_cep[BDIM];               // CE per-row loss
__device__ float d_distp[147];
__device__ float d_angp[147];

// ---------------- f32x2 packed helpers ----------------
__device__ __forceinline__ u64 pk2(float lo, float hi) {
    u64 r; asm("mov.b64 %0,{%1,%2};" : "=l"(r) : "f"(lo), "f"(hi)); return r;
}
__device__ __forceinline__ float2 upk2(u64 v) {
    float2 f; asm("mov.b64 {%0,%1},%2;" : "=f"(f.x), "=f"(f.y) : "l"(v)); return f;
}
__device__ __forceinline__ u64 addx2(u64 a, u64 b) {
    u64 r; asm("add.rn.f32x2 %0,%1,%2;" : "=l"(r) : "l"(a), "l"(b)); return r;
}
__device__ __forceinline__ u64 mulx2(u64 a, u64 b) {
    u64 r; asm("mul.rn.f32x2 %0,%1,%2;" : "=l"(r) : "l"(a), "l"(b)); return r;
}
__device__ __forceinline__ u64 fmx2(u64 a, u64 b, u64 c) {
    u64 r; asm("fma.rn.f32x2 %0,%1,%2,%3;" : "=l"(r) : "l"(a), "l"(b), "l"(c)); return r;
}

__device__ __forceinline__ float block_reduce_256(float v, float* sh8) {
    #pragma unroll
    for (int o = 16; o; o >>= 1) v += __shfl_xor_sync(0xffffffffu, v, o);
    int lane = threadIdx.x & 31, w = threadIdx.x >> 5;
    if (lane == 0) sh8[w] = v;
    __syncthreads();
    v = (threadIdx.x < 8) ? sh8[threadIdx.x] : 0.f;
    if (w == 0) {
        #pragma unroll
        for (int o = 4; o; o >>= 1) v += __shfl_xor_sync(0xffffffffu, v, o);
    }
    return v;  // valid on thread 0
}

// ================= Kernel A: fused GEMM (K-split 2, f32x2) + CE =================
// blocks 0..143 : GEMM tiles (36 tiles x {z in s,t} x {ksplit 0,1})
// blocks 144..527: CE, one row each
__global__ void __launch_bounds__(256) kA(const float* __restrict__ fs,
                                          const float* __restrict__ ft,
                                          const int* __restrict__ lab32) {
    __shared__ float sA[32][64];
    __shared__ float sB[32][64];
    __shared__ float sred[9];
    const int bid = blockIdx.x;
    const int t = threadIdx.x;

    if (bid < 144) {
        const int tile = bid % 36;
        const int zz = bid / 36;
        const int z = zz & 1, kz = zz >> 1;
        const int ti = tile / 6, tj = tile % 6;
        const float* __restrict__ F = z ? ft : fs;
        float* __restrict__ G = z ? (kz ? d_G2t : d_Gt) : (kz ? d_G2s : d_Gs);
        const int i0 = ti * 64, j0 = tj * 64;
        const int kbase = kz * 256;
        const int tx = t & 15, ty = t >> 4;
        const int lr = t & 63, lk = (t >> 6) * 8;

        u64 acc[4][2] = {};
        for (int k0 = 0; k0 < 256; k0 += 32) {
            {
                const float* src = F + (i0 + lr) * CDIM + kbase + k0 + lk;
                float4 v0 = *(const float4*)src;
                float4 v1 = *(const float4*)(src + 4);
                sA[lk + 0][lr] = v0.x; sA[lk + 1][lr] = v0.y;
                sA[lk + 2][lr] = v0.z; sA[lk + 3][lr] = v0.w;
                sA[lk + 4][lr] = v1.x; sA[lk + 5][lr] = v1.y;
                sA[lk + 6][lr] = v1.z; sA[lk + 7][lr] = v1.w;
                const float* srb = F + (j0 + lr) * CDIM + kbase + k0 + lk;
                float4 w0 = *(const float4*)srb;
                float4 w1 = *(const float4*)(srb + 4);
                sB[lk + 0][lr] = w0.x; sB[lk + 1][lr] = w0.y;
                sB[lk + 2][lr] = w0.z; sB[lk + 3][lr] = w0.w;
                sB[lk + 4][lr] = w1.x; sB[lk + 5][lr] = w1.y;
                sB[lk + 6][lr] = w1.z; sB[lk + 7][lr] = w1.w;
            }
            __syncthreads();
            #pragma unroll 8
            for (int kk = 0; kk < 32; kk++) {
                float4 a4 = *(const float4*)&sA[kk][ty * 4];
                const u64* bp = (const u64*)&sB[kk][tx * 4];
                u64 b0 = bp[0], b1 = bp[1];
                u64 a0 = pk2(a4.x, a4.x), a1 = pk2(a4.y, a4.y);
                u64 a2 = pk2(a4.z, a4.z), a3 = pk2(a4.w, a4.w);
                acc[0][0] = fmx2(a0, b0, acc[0][0]); acc[0][1] = fmx2(a0, b1, acc[0][1]);
                acc[1][0] = fmx2(a1, b0, acc[1][0]); acc[1][1] = fmx2(a1, b1, acc[1][1]);
                acc[2][0] = fmx2(a2, b0, acc[2][0]); acc[2][1] = fmx2(a2, b1, acc[2][1]);
                acc[3][0] = fmx2(a3, b0, acc[3][0]); acc[3][1] = fmx2(a3, b1, acc[3][1]);
            }
            __syncthreads();
        }
        #pragma unroll
        for (int a = 0; a < 4; a++) {
            float2 lo = upk2(acc[a][0]), hi = upk2(acc[a][1]);
            float4 v = make_float4(lo.x, lo.y, hi.x, hi.y);
            int gi = i0 + ty * 4 + a;
            *(float4*)(G + gi * BDIM + j0 + tx * 4) = v;
            if (ti == tj) {
                int c = gi - (j0 + tx * 4);
                if (c >= 0 && c < 4) d_dg[z][kz][gi] = (&v.x)[c];
            }
        }
    } else {
        // ---------------- CE: one row per block, 256 threads ----------------
        const int r = bid - 144;
        const float* __restrict__ x = fs + r * CDIM;
        float v0 = x[t], v1 = x[t + 256];
        // label width detect (int64 labels < 512 -> all odd words zero)
        int hi = (t < 192) ? lab32[2 * t + 1] : 0;
        int is64 = !__syncthreads_or(hi != 0);

        float m = fmaxf(v0, v1);
        #pragma unroll
        for (int o = 16; o; o >>= 1) m = fmaxf(m, __shfl_xor_sync(0xffffffffu, m, o));
        if ((t & 31) == 0) sred[t >> 5] = m;
        __syncthreads();
        float M = sred[0];
        #pragma unroll
        for (int w = 1; w < 8; w++) M = fmaxf(M, sred[w]);
        float s = expf(v0 - M) + expf(v1 - M);
        __syncthreads();
        s = block_reduce_256(s, sred);
        if (t == 0) {
            int L = lab32[is64 ? 2 * r : r];
            d_cep[r] = (logf(s) + M) - x[L];
        }
    }
}

// ================= Kernel B: combine G, iD, diag, sum(D) =================
__global__ void __launch_bounds__(256) kB() {
    __shared__ float sred[9];
    const int z = blockIdx.y;
    float* __restrict__ G1 = z ? d_Gt : d_Gs;
    const float* __restrict__ G2 = z ? d_G2t : d_G2s;
    float* __restrict__ iD = z ? d_iDt : d_iDs;
    const float* dg0 = d_dg[z][0];
    const float* dg1 = d_dg[z][1];
    const int base = blockIdx.x * 1024;
    float part = 0.f;
    #pragma unroll
    for (int q = 0; q < 4; q++) {
        int e = base + q * 256 + threadIdx.x;
        int i = e / BDIM;
        int j = e - i * BDIM;
        float g = G1[e] + G2[e];
        G1[e] = g;   // combined G (diag reads go through d_dg, no race)
        if (i == j) {
            iD[e] = 0.f;
            d_sqA[z][i] = dg0[i] + dg1[i];
        } else {
            float sqi = dg0[i] + dg1[i];
            float sqj = dg0[j] + dg1[j];
            float d = sqrtf(fmaxf(sqi + sqj - 2.f * g, 1e-12f));
            iD[e] = 1.f / d;
            part += d;
        }
    }
    part = block_reduce_256(part, sred);
    if (threadIdx.x == 0) d_dsum[z * 144 + blockIdx.x] = part;
}

// ================= Kernel C: angle smooth-L1 (f32x2) + dist smooth-L1 =================
// grid (21, 7): 21 symmetric 64x64 (i,j) tile-pairs x 7 b-slices.
// Each block also handles a 1/147 slice of the B^2 dist loss.
__global__ void __launch_bounds__(256) kC() {
    __shared__ float sred[9];
    __shared__ float ssum[2];
    const int fid = blockIdx.y * 21 + blockIdx.x;
    int rem = blockIdx.x, ti = 0;
    while (rem >= 6 - ti) { rem -= 6 - ti; ti++; }
    const int tj = ti + rem;
    const int t = threadIdx.x;
    const int tx = t & 15, ty = t >> 4;
    const int i0 = ti * 64 + ty * 4;
    const int j0 = tj * 64 + tx * 4;

    // ---- dist mean sums (fixed-order reduce of pdist partials) ----
    {
        float ps = (t < 144) ? d_dsum[t] : 0.f;
        float pt = (t < 144) ? d_dsum[144 + t] : 0.f;
        ps = block_reduce_256(ps, sred);
        if (t == 0) ssum[0] = ps;
        __syncthreads();
        pt = block_reduce_256(pt, sred);
        if (t == 0) ssum[1] = pt;
        __syncthreads();
    }
    const float ims = 147072.f / ssum[0];
    const float imt = 147072.f / ssum[1];

    // ---- dist slice ----
    float dacc = 0.f;
    {
        int e0 = (fid * B2) / 147, e1 = ((fid + 1) * B2) / 147;
        for (int e = e0 + t; e < e1; e += 256) {
            int i = e / BDIM;
            int j = e - i * BDIM;
            float dS = 0.f, dT = 0.f;
            if (i != j) {
                float gS = d_Gs[e], gT = d_Gt[e];
                dS = sqrtf(fmaxf(d_sqA[0][i] + d_sqA[0][j] - 2.f * gS, 1e-12f));
                dT = sqrtf(fmaxf(d_sqA[1][i] + d_sqA[1][j] - 2.f * gT, 1e-12f));
            }
            float a = fabsf(dS * ims - dT * imt);
            float mm = fminf(a, 1.f);
            dacc = fmaf(mm, fmaf(-0.5f, mm, a), dacc);
        }
    }

    // ---- angle: preload G tiles packed along j ----
    u64 g2S[4][2], g2T[4][2];
    #pragma unroll
    for (int a = 0; a < 4; a++) {
        float4 v = *(const float4*)(d_Gs + (i0 + a) * BDIM + j0);
        g2S[a][0] = pk2(v.x, v.y); g2S[a][1] = pk2(v.z, v.w);
        float4 w = *(const float4*)(d_Gt + (i0 + a) * BDIM + j0);
        g2T[a][0] = pk2(w.x, w.y); g2T[a][1] = pk2(w.z, w.w);
    }
    const u64 M1 = pk2(-1.f, -1.f);
    const int b0 = (blockIdx.y * BDIM) / 7;
    const int b1 = ((blockIdx.y + 1) * BDIM) / 7;

    float acc0 = 0.f, acc1 = 0.f, acc2 = 0.f, acc3 = 0.f;
    for (int b = b0; b < b1; b++) {
        const int ro = b * BDIM;
        float4 gbiS = *(const float4*)(d_Gs + ro + i0);
        float4 ibiS = *(const float4*)(d_iDs + ro + i0);
        float4 gbjS = *(const float4*)(d_Gs + ro + j0);
        float4 ibjS = *(const float4*)(d_iDs + ro + j0);
        float4 gbiT = *(const float4*)(d_Gt + ro + i0);
        float4 ibiT = *(const float4*)(d_iDt + ro + i0);
        float4 gbjT = *(const float4*)(d_Gt + ro + j0);
        float4 ibjT = *(const float4*)(d_iDt + ro + j0);
        float sqS = d_sqA[0][b], sqT = d_sqA[1][b];

        u64 gbj2S[2] = { pk2(gbjS.x, gbjS.y), pk2(gbjS.z, gbjS.w) };
        u64 gbj2T[2] = { pk2(gbjT.x, gbjT.y), pk2(gbjT.z, gbjT.w) };
        u64 uj2S[2]  = { pk2(ibjS.x, ibjS.y), pk2(ibjS.z, ibjS.w) };
        u64 uj2T[2]  = { pk2(ibjT.x, ibjT.y), pk2(ibjT.z, ibjT.w) };

        u64 si2S[4], si2T[4], uu2S[4][2], uu2T[4][2];
        {
            float s0 = sqS - gbiS.x, s1 = sqS - gbiS.y, s2 = sqS - gbiS.z, s3 = sqS - gbiS.w;
            si2S[0] = pk2(s0, s0); si2S[1] = pk2(s1, s1);
            si2S[2] = pk2(s2, s2); si2S[3] = pk2(s3, s3);
            float t0 = sqT - gbiT.x, t1 = sqT - gbiT.y, t2 = sqT - gbiT.z, t3 = sqT - gbiT.w;
            si2T[0] = pk2(t0, t0); si2T[1] = pk2(t1, t1);
            si2T[2] = pk2(t2, t2); si2T[3] = pk2(t3, t3);
            u64 uiS[4] = { pk2(ibiS.x, ibiS.x), pk2(ibiS.y, ibiS.y),
                           pk2(ibiS.z, ibiS.z), pk2(ibiS.w, ibiS.w) };
            u64 uiT[4] = { pk2(ibiT.x, ibiT.x), pk2(ibiT.y, ibiT.y),
                           pk2(ibiT.z, ibiT.z), pk2(ibiT.w, ibiT.w) };
            #pragma unroll
            for (int a = 0; a < 4; a++) {
                uu2S[a][0] = mulx2(uiS[a], uj2S[0]); uu2S[a][1] = mulx2(uiS[a], uj2S[1]);
                uu2T[a][0] = mulx2(uiT[a], uj2T[0]); uu2T[a][1] = mulx2(uiT[a], uj2T[1]);
            }
        }

        #pragma unroll
        for (int a = 0; a < 4; a++) {
            float la = 0.f;
            #pragma unroll
            for (int p = 0; p < 2; p++) {
                u64 wS = fmx2(gbj2S[p], M1, si2S[a]);           // si - gbj
                u64 vS = mulx2(addx2(g2S[a][p], wS), uu2S[a][p]);
                u64 wT = fmx2(gbj2T[p], M1, si2T[a]);
                u64 vT = mulx2(addx2(g2T[a][p], wT), uu2T[a][p]);
                float2 d = upk2(fmx2(vT, M1, vS));              // vs - vt
                float a0 = fabsf(d.x), m0 = fminf(a0, 1.f);
                la = fmaf(m0, fmaf(-0.5f, m0, a0), la);
                float a1 = fabsf(d.y), m1 = fminf(a1, 1.f);
                la = fmaf(m1, fmaf(-0.5f, m1, a1), la);
            }
            if (a == 0) acc0 += la; else if (a == 1) acc1 += la;
            else if (a == 2) acc2 += la; else acc3 += la;
        }
    }
    float aacc = (acc0 + acc1) + (acc2 + acc3);
    if (ti != tj) aacc *= 2.f;

    __syncthreads();
    aacc = block_reduce_256(aacc, sred);
    if (t == 0) d_angp[fid] = aacc;
    __syncthreads();
    dacc = block_reduce_256(dacc, sred);
    if (t == 0) d_distp[fid] = dacc;
}

// ================= Kernel D: finalize =================
__global__ void __launch_bounds__(256) kD(float* __restrict__ out, int n) {
    __shared__ double dsh[8];
    const int t = threadIdx.x;
    double ce = 0.0, di = 0.0, an = 0.0;
    for (int i = t; i < BDIM; i += 256) ce += (double)d_cep[i];
    if (t < 147) { di = (double)d_distp[t]; an = (double)d_angp[t]; }

    // deterministic block reduction of three doubles
    #pragma unroll
    for (int o = 16; o; o >>= 1) {
        ce += __shfl_xor_sync(0xffffffffu, ce, o);
        di += __shfl_xor_sync(0xffffffffu, di, o);
        an += __shfl_xor_sync(0xffffffffu, an, o);
    }
    int lane = t & 31, w = t >> 5;
    if (lane == 0) dsh[w] = ce;
    __syncthreads();
    if (t == 0) { for (int i = 1; i < 8; i++) ce += dsh[i]; }
    __syncthreads();
    if (lane == 0) dsh[w] = di;
    __syncthreads();
    if (t == 0) { for (int i = 1; i < 8; i++) di += dsh[i]; }
    __syncthreads();
    if (lane == 0) dsh[w] = an;
    __syncthreads();
    if (t == 0) { for (int i = 1; i < 8; i++) an += dsh[i]; }
    __syncthreads();

    for (int i = t; i < n; i += 256) out[i] = 0.f;
    if (t == 0) {
        double tot = ce / (double)BDIM
                   + di / (double)B2
                   + an / ((double)BDIM * (double)B2);
        out[0] = (float)tot;
    }
}

// ================= launch =================
extern "C" void kernel_launch(void* const* d_in, const int* in_sizes, int n_in,
                              void* d_out, int out_size) {
    const float* fs = (const float*)d_in[0];
    const float* ft = (const float*)d_in[1];
    const int* lb = (const int*)d_in[2];
    float* out = (float*)d_out;

    kA<<<528, 256>>>(fs, ft, lb);
    kB<<<dim3(144, 2), 256>>>();
    kC<<<dim3(21, 7), 256>>>();
    kD<<<1, 256>>>(out, out_size);
}

// round 5
// speedup vs baseline: 1.0651x; 1.0622x over previous
#include <cuda_runtime.h>

typedef unsigned long long u64;
#define BDIM 384
#define CDIM 512
#define B2   147456   // 384*384
#define NBLK 148

// ---------------- scratch (no allocations allowed) ----------------
__device__ __align__(16) float d_Gs[B2];    // K-split part 0 (s), later combined G
__device__ __align__(16) float d_Gt[B2];
__device__ __align__(16) float d_G2s[B2];   // K-split part 1
__device__ __align__(16) float d_G2t[B2];
__device__ __align__(16) float d_iDs[B2];
__device__ __align__(16) float d_iDt[B2];
__device__ __align__(16) float d_dg[2][2][BDIM];   // diag partials [z][ksplit][i]
__device__ __align__(16) float d_sqA[2][BDIM];     // combined diag (sq norms)
__device__ __align__(16) float d_dsum[2 * NBLK];   // pdist partial sums [z][blk]
__device__ __align__(16) float d_cep[BDIM];        // CE per-row loss
__device__ __align__(16) float d_distp[NBLK];
__device__ __align__(16) float d_angp[NBLK];
__device__ unsigned d_barcnt;
__device__ int d_labmode;    // 1 = labels int64, 0 = int32

// ---------------- f32x2 packed helpers ----------------
__device__ __forceinline__ u64 pk2(float lo, float hi) {
    u64 r; asm("mov.b64 %0,{%1,%2};" : "=l"(r) : "f"(lo), "f"(hi)); return r;
}
__device__ __forceinline__ float2 upk2(u64 v) {
    float2 f; asm("mov.b64 {%0,%1},%2;" : "=f"(f.x), "=f"(f.y) : "l"(v)); return f;
}
__device__ __forceinline__ u64 addx2(u64 a, u64 b) {
    u64 r; asm("add.rn.f32x2 %0,%1,%2;" : "=l"(r) : "l"(a), "l"(b)); return r;
}
__device__ __forceinline__ u64 mulx2(u64 a, u64 b) {
    u64 r; asm("mul.rn.f32x2 %0,%1,%2;" : "=l"(r) : "l"(a), "l"(b)); return r;
}
__device__ __forceinline__ u64 fmx2(u64 a, u64 b, u64 c) {
    u64 r; asm("fma.rn.f32x2 %0,%1,%2,%3;" : "=l"(r) : "l"(a), "l"(b), "l"(c)); return r;
}

__device__ __forceinline__ float block_reduce_256(float v, float* sh8) {
    #pragma unroll
    for (int o = 16; o; o >>= 1) v += __shfl_xor_sync(0xffffffffu, v, o);
    int lane = threadIdx.x & 31, w = threadIdx.x >> 5;
    if (lane == 0) sh8[w] = v;
    __syncthreads();
    v = (threadIdx.x < 8) ? sh8[threadIdx.x] : 0.f;
    if (w == 0) {
        #pragma unroll
        for (int o = 4; o; o >>= 1) v += __shfl_xor_sync(0xffffffffu, v, o);
    }
    __syncthreads();
    return v;  // valid on thread 0
}

// ---------------- software grid barrier (all NBLK blocks resident) ----------------
__device__ __forceinline__ void gridbar(unsigned target) {
    __syncthreads();
    if (threadIdx.x == 0) {
        __threadfence();                       // release all prior writes (gpu scope)
        atomicAdd(&d_barcnt, 1u);
        unsigned v;
        do {
            asm volatile("ld.acquire.gpu.u32 %0,[%1];" : "=r"(v) : "l"(&d_barcnt));
        } while (v < target);
    }
    __syncthreads();
}

// ---------------- init: reset barrier counter ----------------
__global__ void kInit() { d_barcnt = 0u; }

// ================= THE persistent kernel =================
__global__ void __launch_bounds__(256) kMain(const float* __restrict__ fs,
                                             const float* __restrict__ ft,
                                             const int* __restrict__ lab32,
                                             float* __restrict__ out, int nout) {
    __shared__ float sA[32][64];
    __shared__ float sB[32][64];
    __shared__ float sred[9];
    __shared__ float ssum[2];
    const int bid = blockIdx.x;
    const int t = threadIdx.x;
    const int lane = t & 31, wid = t >> 5;

    // ========== Phase 1: GEMM (K-split 2, f32x2), 144 jobs ==========
    if (bid < 144) {
        const int tile = bid % 36;
        const int zz = bid / 36;
        const int z = zz & 1, kz = zz >> 1;
        const int ti = tile / 6, tj = tile % 6;
        const float* __restrict__ F = z ? ft : fs;
        float* __restrict__ G = z ? (kz ? d_G2t : d_Gt) : (kz ? d_G2s : d_Gs);
        const int i0 = ti * 64, j0 = tj * 64;
        const int kbase = kz * 256;
        const int tx = t & 15, ty = t >> 4;
        const int lr = t & 63, lk = (t >> 6) * 8;

        u64 acc[4][2] = {};
        for (int k0 = 0; k0 < 256; k0 += 32) {
            {
                const float* src = F + (i0 + lr) * CDIM + kbase + k0 + lk;
                float4 v0 = *(const float4*)src;
                float4 v1 = *(const float4*)(src + 4);
                sA[lk + 0][lr] = v0.x; sA[lk + 1][lr] = v0.y;
                sA[lk + 2][lr] = v0.z; sA[lk + 3][lr] = v0.w;
                sA[lk + 4][lr] = v1.x; sA[lk + 5][lr] = v1.y;
                sA[lk + 6][lr] = v1.z; sA[lk + 7][lr] = v1.w;
                const float* srb = F + (j0 + lr) * CDIM + kbase + k0 + lk;
                float4 w0 = *(const float4*)srb;
                float4 w1 = *(const float4*)(srb + 4);
                sB[lk + 0][lr] = w0.x; sB[lk + 1][lr] = w0.y;
                sB[lk + 2][lr] = w0.z; sB[lk + 3][lr] = w0.w;
                sB[lk + 4][lr] = w1.x; sB[lk + 5][lr] = w1.y;
                sB[lk + 6][lr] = w1.z; sB[lk + 7][lr] = w1.w;
            }
            __syncthreads();
            #pragma unroll 8
            for (int kk = 0; kk < 32; kk++) {
                float4 a4 = *(const float4*)&sA[kk][ty * 4];
                const u64* bp = (const u64*)&sB[kk][tx * 4];
                u64 b0 = bp[0], b1 = bp[1];
                u64 a0 = pk2(a4.x, a4.x), a1 = pk2(a4.y, a4.y);
                u64 a2 = pk2(a4.z, a4.z), a3 = pk2(a4.w, a4.w);
                acc[0][0] = fmx2(a0, b0, acc[0][0]); acc[0][1] = fmx2(a0, b1, acc[0][1]);
                acc[1][0] = fmx2(a1, b0, acc[1][0]); acc[1][1] = fmx2(a1, b1, acc[1][1]);
                acc[2][0] = fmx2(a2, b0, acc[2][0]); acc[2][1] = fmx2(a2, b1, acc[2][1]);
                acc[3][0] = fmx2(a3, b0, acc[3][0]); acc[3][1] = fmx2(a3, b1, acc[3][1]);
            }
            __syncthreads();
        }
        #pragma unroll
        for (int a = 0; a < 4; a++) {
            float2 lo = upk2(acc[a][0]), hi = upk2(acc[a][1]);
            float4 v = make_float4(lo.x, lo.y, hi.x, hi.y);
            int gi = i0 + ty * 4 + a;
            *(float4*)(G + gi * BDIM + j0 + tx * 4) = v;
            if (ti == tj) {
                int c = gi - (j0 + tx * 4);
                if (c >= 0 && c < 4) d_dg[z][kz][gi] = (&v.x)[c];
            }
        }
    } else if (bid == 147 && wid == 0) {
        // label width detect: int64 labels < 512 -> every odd int32 word is 0
        int hi = 0;
        #pragma unroll
        for (int k = 0; k < 6; k++) hi |= lab32[2 * (lane + 32 * k) + 1];
        unsigned any = __ballot_sync(0xffffffffu, hi != 0);
        if (lane == 0) d_labmode = any ? 0 : 1;
    }

    gridbar(NBLK);  // ---- barrier 1 ----

    // ========== Phase 2: combine G, invD, diag, sum(D) + CE ==========
    {
        // CE: warp-per-row (384 rows over 1184 warps)
        const int gw = bid * 8 + wid;
        if (gw < BDIM) {
            const float* __restrict__ x = fs + gw * CDIM;
            float4 v[4];
            #pragma unroll
            for (int k = 0; k < 4; k++)
                v[k] = *(const float4*)(x + lane * 4 + 128 * k);
            float m = fmaxf(fmaxf(fmaxf(v[0].x, v[0].y), fmaxf(v[0].z, v[0].w)),
                            fmaxf(fmaxf(v[1].x, v[1].y), fmaxf(v[1].z, v[1].w)));
            m = fmaxf(m, fmaxf(fmaxf(fmaxf(v[2].x, v[2].y), fmaxf(v[2].z, v[2].w)),
                               fmaxf(fmaxf(v[3].x, v[3].y), fmaxf(v[3].z, v[3].w))));
            #pragma unroll
            for (int o = 16; o; o >>= 1) m = fmaxf(m, __shfl_xor_sync(0xffffffffu, m, o));
            float s = 0.f;
            #pragma unroll
            for (int k = 0; k < 4; k++)
                s += expf(v[k].x - m) + expf(v[k].y - m) + expf(v[k].z - m) + expf(v[k].w - m);
            #pragma unroll
            for (int o = 16; o; o >>= 1) s += __shfl_xor_sync(0xffffffffu, s, o);
            if (lane == 0) {
                int L = lab32[d_labmode ? 2 * gw : gw];
                d_cep[gw] = (logf(s) + m) - x[L];
            }
        }

        float dz0 = 0.f, dz1 = 0.f;
        for (int e = bid * 256 + t; e < 2 * B2; e += NBLK * 256) {
            int z = (e >= B2);
            int ee = e - (z ? B2 : 0);
            int i = ee / BDIM;
            int j = ee - i * BDIM;
            float* __restrict__ G1 = z ? d_Gt : d_Gs;
            const float* __restrict__ G2 = z ? d_G2t : d_G2s;
            float* __restrict__ iD = z ? d_iDt : d_iDs;
            float g = G1[ee] + G2[ee];
            G1[ee] = g;
            float si = d_dg[z][0][i] + d_dg[z][1][i];
            if (i == j) {
                iD[ee] = 0.f;
                d_sqA[z][i] = si;
            } else {
                float sj = d_dg[z][0][j] + d_dg[z][1][j];
                float d = sqrtf(fmaxf(si + sj - 2.f * g, 1e-12f));
                iD[ee] = 1.f / d;
                if (z) dz1 += d; else dz0 += d;
            }
        }
        dz0 = block_reduce_256(dz0, sred);
        if (t == 0) d_dsum[bid] = dz0;
        dz1 = block_reduce_256(dz1, sred);
        if (t == 0) d_dsum[NBLK + bid] = dz1;
    }

    gridbar(2 * NBLK);  // ---- barrier 2 ----

    // ========== Phase 3: angle smooth-L1 (f32x2) + dist smooth-L1 ==========
    // every block reduces the Σd partials (identical fixed order -> deterministic)
    {
        float ps = (t < NBLK) ? d_dsum[t] : 0.f;
        float pt2 = (t < NBLK) ? d_dsum[NBLK + t] : 0.f;
        ps = block_reduce_256(ps, sred);
        if (t == 0) ssum[0] = ps;
        pt2 = block_reduce_256(pt2, sred);
        if (t == 0) ssum[1] = pt2;
        __syncthreads();
    }

    if (bid < 147) {
        const float ims = 147072.f / ssum[0];
        const float imt = 147072.f / ssum[1];
        const int bx = bid % 21, by = bid / 21;
        int rem = bx, ti = 0;
        while (rem >= 6 - ti) { rem -= 6 - ti; ti++; }
        const int tj = ti + rem;
        const int tx = t & 15, ty = t >> 4;
        const int i0 = ti * 64 + ty * 4;
        const int j0 = tj * 64 + tx * 4;

        // ---- dist slice (1/147 of B^2) ----
        float dacc = 0.f;
        {
            int e0 = (bid * B2) / 147, e1 = ((bid + 1) * B2) / 147;
            for (int e = e0 + t; e < e1; e += 256) {
                int i = e / BDIM;
                int j = e - i * BDIM;
                float dS = 0.f, dT = 0.f;
                if (i != j) {
                    float gS = d_Gs[e], gT = d_Gt[e];
                    dS = sqrtf(fmaxf(d_sqA[0][i] + d_sqA[0][j] - 2.f * gS, 1e-12f));
                    dT = sqrtf(fmaxf(d_sqA[1][i] + d_sqA[1][j] - 2.f * gT, 1e-12f));
                }
                float a = fabsf(dS * ims - dT * imt);
                float mm = fminf(a, 1.f);
                dacc = fmaf(mm, fmaf(-0.5f, mm, a), dacc);
            }
        }

        // ---- angle tile ----
        u64 g2S[4][2], g2T[4][2];
        #pragma unroll
        for (int a = 0; a < 4; a++) {
            float4 v = *(const float4*)(d_Gs + (i0 + a) * BDIM + j0);
            g2S[a][0] = pk2(v.x, v.y); g2S[a][1] = pk2(v.z, v.w);
            float4 w = *(const float4*)(d_Gt + (i0 + a) * BDIM + j0);
            g2T[a][0] = pk2(w.x, w.y); g2T[a][1] = pk2(w.z, w.w);
        }
        const u64 M1 = pk2(-1.f, -1.f);
        const int b0 = (by * BDIM) / 7;
        const int b1 = ((by + 1) * BDIM) / 7;

        float acc0 = 0.f, acc1 = 0.f, acc2 = 0.f, acc3 = 0.f;
        for (int b = b0; b < b1; b++) {
            const int ro = b * BDIM;
            float4 gbiS = *(const float4*)(d_Gs + ro + i0);
            float4 ibiS = *(const float4*)(d_iDs + ro + i0);
            float4 gbjS = *(const float4*)(d_Gs + ro + j0);
            float4 ibjS = *(const float4*)(d_iDs + ro + j0);
            float4 gbiT = *(const float4*)(d_Gt + ro + i0);
            float4 ibiT = *(const float4*)(d_iDt + ro + i0);
            float4 gbjT = *(const float4*)(d_Gt + ro + j0);
            float4 ibjT = *(const float4*)(d_iDt + ro + j0);
            float sqS = d_sqA[0][b], sqT = d_sqA[1][b];

            u64 gbj2S[2] = { pk2(gbjS.x, gbjS.y), pk2(gbjS.z, gbjS.w) };
            u64 gbj2T[2] = { pk2(gbjT.x, gbjT.y), pk2(gbjT.z, gbjT.w) };
            u64 uj2S[2]  = { pk2(ibjS.x, ibjS.y), pk2(ibjS.z, ibjS.w) };
            u64 uj2T[2]  = { pk2(ibjT.x, ibjT.y), pk2(ibjT.z, ibjT.w) };

            u64 si2S[4], si2T[4], uu2S[4][2], uu2T[4][2];
            {
                float s0 = sqS - gbiS.x, s1 = sqS - gbiS.y, s2 = sqS - gbiS.z, s3 = sqS - gbiS.w;
                si2S[0] = pk2(s0, s0); si2S[1] = pk2(s1, s1);
                si2S[2] = pk2(s2, s2); si2S[3] = pk2(s3, s3);
                float t0 = sqT - gbiT.x, t1 = sqT - gbiT.y, t2 = sqT - gbiT.z, t3 = sqT - gbiT.w;
                si2T[0] = pk2(t0, t0); si2T[1] = pk2(t1, t1);
                si2T[2] = pk2(t2, t2); si2T[3] = pk2(t3, t3);
                u64 uiS[4] = { pk2(ibiS.x, ibiS.x), pk2(ibiS.y, ibiS.y),
                               pk2(ibiS.z, ibiS.z), pk2(ibiS.w, ibiS.w) };
                u64 uiT[4] = { pk2(ibiT.x, ibiT.x), pk2(ibiT.y, ibiT.y),
                               pk2(ibiT.z, ibiT.z), pk2(ibiT.w, ibiT.w) };
                #pragma unroll
                for (int a = 0; a < 4; a++) {
                    uu2S[a][0] = mulx2(uiS[a], uj2S[0]); uu2S[a][1] = mulx2(uiS[a], uj2S[1]);
                    uu2T[a][0] = mulx2(uiT[a], uj2T[0]); uu2T[a][1] = mulx2(uiT[a], uj2T[1]);
                }
            }

            #pragma unroll
            for (int a = 0; a < 4; a++) {
                float la = 0.f;
                #pragma unroll
                for (int p = 0; p < 2; p++) {
                    u64 wS = fmx2(gbj2S[p], M1, si2S[a]);          // si - gbj
                    u64 vS = mulx2(addx2(g2S[a][p], wS), uu2S[a][p]);
                    u64 wT = fmx2(gbj2T[p], M1, si2T[a]);
                    u64 vT = mulx2(addx2(g2T[a][p], wT), uu2T[a][p]);
                    float2 d = upk2(fmx2(vT, M1, vS));             // vs - vt
                    float a0 = fabsf(d.x), m0 = fminf(a0, 1.f);
                    la = fmaf(m0, fmaf(-0.5f, m0, a0), la);
                    float a1 = fabsf(d.y), m1 = fminf(a1, 1.f);
                    la = fmaf(m1, fmaf(-0.5f, m1, a1), la);
                }
                if (a == 0) acc0 += la; else if (a == 1) acc1 += la;
                else if (a == 2) acc2 += la; else acc3 += la;
            }
        }
        float aacc = (acc0 + acc1) + (acc2 + acc3);
        if (ti != tj) aacc *= 2.f;

        aacc = block_reduce_256(aacc, sred);
        if (t == 0) d_angp[bid] = aacc;
        dacc = block_reduce_256(dacc, sred);
        if (t == 0) d_distp[bid] = dacc;
    }

    gridbar(3 * NBLK);  // ---- barrier 3 ----

    // ========== Phase 4: finalize (block 0) ==========
    if (bid == 0) {
        __shared__ double dsh[8];
        double ce = 0.0, di = 0.0, an = 0.0;
        for (int i = t; i < BDIM; i += 256) ce += (double)d_cep[i];
        if (t < 147) { di = (double)d_distp[t]; an = (double)d_angp[t]; }
        #pragma unroll
        for (int o = 16; o; o >>= 1) {
            ce += __shfl_xor_sync(0xffffffffu, ce, o);
            di += __shfl_xor_sync(0xffffffffu, di, o);
            an += __shfl_xor_sync(0xffffffffu, an, o);
        }
        if (lane == 0) dsh[wid] = ce;
        __syncthreads();
        if (t == 0) { for (int i = 1; i < 8; i++) ce += dsh[i]; }
        __syncthreads();
        if (lane == 0) dsh[wid] = di;
        __syncthreads();
        if (t == 0) { for (int i = 1; i < 8; i++) di += dsh[i]; }
        __syncthreads();
        if (lane == 0) dsh[wid] = an;
        __syncthreads();
        if (t == 0) { for (int i = 1; i < 8; i++) an += dsh[i]; }
        __syncthreads();

        for (int i = t; i < nout; i += 256) out[i] = 0.f;
        if (t == 0) {
            double tot = ce / (double)BDIM
                       + di / (double)B2
                       + an / ((double)BDIM * (double)B2);
            out[0] = (float)tot;
        }
    }
}

// ================= launch =================
extern "C" void kernel_launch(void* const* d_in, const int* in_sizes, int n_in,
                              void* d_out, int out_size) {
    const float* fs = (const float*)d_in[0];
    const float* ft = (const float*)d_in[1];
    const int* lb = (const int*)d_in[2];
    float* out = (float*)d_out;

    kInit<<<1, 1>>>();
    kMain<<<NBLK, 256>>>(fs, ft, lb, out, out_size);
}

// round 6
// speedup vs baseline: 1.3473x; 1.2649x over previous
#include <cuda_runtime.h>

typedef unsigned long long u64;
#define BDIM 384
#define CDIM 512
#define B2   147456          // 384*384
#define NBLK 296             // 2 CTAs per SM * 148 SMs

// ---------------- scratch (no allocations allowed) ----------------
// G partials: slot (kz*2+z); kz=0 slot becomes the combined G after phase 2.
__device__ __align__(16) float d_Gbig[8 * B2];
__device__ __align__(16) float d_iDs[B2];
__device__ __align__(16) float d_iDt[B2];
__device__ __align__(16) float d_dg[4][2][BDIM];   // diag partials [kz][z][i]
__device__ __align__(16) float d_dsum[2 * NBLK];   // pdist partial sums [z][blk]
__device__ __align__(16) float d_cep[BDIM];        // CE per-row loss
__device__ __align__(16) float d_distp[NBLK];
__device__ __align__(16) float d_angp[NBLK];
__device__ unsigned d_barcnt;
__device__ int d_labmode;    // 1 = labels int64, 0 = int32

// ---------------- f32x2 packed helpers ----------------
__device__ __forceinline__ u64 pk2(float lo, float hi) {
    u64 r; asm("mov.b64 %0,{%1,%2};" : "=l"(r) : "f"(lo), "f"(hi)); return r;
}
__device__ __forceinline__ float2 upk2(u64 v) {
    float2 f; asm("mov.b64 {%0,%1},%2;" : "=f"(f.x), "=f"(f.y) : "l"(v)); return f;
}
__device__ __forceinline__ u64 addx2(u64 a, u64 b) {
    u64 r; asm("add.rn.f32x2 %0,%1,%2;" : "=l"(r) : "l"(a), "l"(b)); return r;
}
__device__ __forceinline__ u64 mulx2(u64 a, u64 b) {
    u64 r; asm("mul.rn.f32x2 %0,%1,%2;" : "=l"(r) : "l"(a), "l"(b)); return r;
}
__device__ __forceinline__ u64 fmx2(u64 a, u64 b, u64 c) {
    u64 r; asm("fma.rn.f32x2 %0,%1,%2,%3;" : "=l"(r) : "l"(a), "l"(b), "l"(c)); return r;
}

__device__ __forceinline__ float block_reduce_256(float v, float* sh8) {
    #pragma unroll
    for (int o = 16; o; o >>= 1) v += __shfl_xor_sync(0xffffffffu, v, o);
    int lane = threadIdx.x & 31, w = threadIdx.x >> 5;
    if (lane == 0) sh8[w] = v;
    __syncthreads();
    v = (threadIdx.x < 8) ? sh8[threadIdx.x] : 0.f;
    if (w == 0) {
        #pragma unroll
        for (int o = 4; o; o >>= 1) v += __shfl_xor_sync(0xffffffffu, v, o);
    }
    __syncthreads();
    return v;  // valid on thread 0
}

// ---------------- software grid barrier (all NBLK blocks resident) ----------------
__device__ __forceinline__ void gridbar(unsigned target) {
    __syncthreads();
    if (threadIdx.x == 0) {
        __threadfence();
        atomicAdd(&d_barcnt, 1u);
        unsigned v;
        do {
            asm volatile("ld.acquire.gpu.u32 %0,[%1];" : "=r"(v) : "l"(&d_barcnt));
        } while (v < target);
    }
    __syncthreads();
}

__global__ void kInit() { d_barcnt = 0u; }

// ================= THE persistent kernel =================
__global__ void __launch_bounds__(256, 2) kMain(const float* __restrict__ fs,
                                                const float* __restrict__ ft,
                                                const int* __restrict__ lab32,
                                                float* __restrict__ out, int nout) {
    __shared__ u64   sA2[32][64];     // A tile, each element pre-duplicated (a,a)
    __shared__ float sB[32][64];
    __shared__ float s_sq[2 * BDIM];  // combined sq norms, reused in phases 2-3
    __shared__ float sred[9];
    __shared__ float ssum[2];
    const int bid = blockIdx.x;
    const int t = threadIdx.x;
    const int lane = t & 31, wid = t >> 5;

    // ========== Phase 1: GEMM (K-split 4, f32x2, dup-A smem), 288 jobs ==========
    if (bid < 288) {
        const int tile = bid % 36;
        const int zz = bid / 36;          // 0..7
        const int z = zz & 1, kz = zz >> 1;
        const float* __restrict__ F = z ? ft : fs;
        float* __restrict__ G = d_Gbig + (kz * 2 + z) * B2;
        const int i0 = (tile / 6) * 64, j0 = (tile % 6) * 64;
        const int kbase = kz * 128;
        const int tx = t & 15, ty = t >> 4;
        const int lr = t & 63, lk = (t >> 6) * 8;

        u64 acc[4][2] = {};
        for (int k0 = 0; k0 < 128; k0 += 32) {
            {
                const float* src = F + (i0 + lr) * CDIM + kbase + k0 + lk;
                float4 v0 = *(const float4*)src;
                float4 v1 = *(const float4*)(src + 4);
                sA2[lk + 0][lr] = pk2(v0.x, v0.x); sA2[lk + 1][lr] = pk2(v0.y, v0.y);
                sA2[lk + 2][lr] = pk2(v0.z, v0.z); sA2[lk + 3][lr] = pk2(v0.w, v0.w);
                sA2[lk + 4][lr] = pk2(v1.x, v1.x); sA2[lk + 5][lr] = pk2(v1.y, v1.y);
                sA2[lk + 6][lr] = pk2(v1.z, v1.z); sA2[lk + 7][lr] = pk2(v1.w, v1.w);
                const float* srb = F + (j0 + lr) * CDIM + kbase + k0 + lk;
                float4 w0 = *(const float4*)srb;
                float4 w1 = *(const float4*)(srb + 4);
                sB[lk + 0][lr] = w0.x; sB[lk + 1][lr] = w0.y;
                sB[lk + 2][lr] = w0.z; sB[lk + 3][lr] = w0.w;
                sB[lk + 4][lr] = w1.x; sB[lk + 5][lr] = w1.y;
                sB[lk + 6][lr] = w1.z; sB[lk + 7][lr] = w1.w;
            }
            __syncthreads();
            #pragma unroll 8
            for (int kk = 0; kk < 32; kk++) {
                u64 a0 = sA2[kk][ty * 4 + 0], a1 = sA2[kk][ty * 4 + 1];
                u64 a2 = sA2[kk][ty * 4 + 2], a3 = sA2[kk][ty * 4 + 3];
                const u64* bp = (const u64*)&sB[kk][tx * 4];
                u64 b0 = bp[0], b1 = bp[1];
                acc[0][0] = fmx2(a0, b0, acc[0][0]); acc[0][1] = fmx2(a0, b1, acc[0][1]);
                acc[1][0] = fmx2(a1, b0, acc[1][0]); acc[1][1] = fmx2(a1, b1, acc[1][1]);
                acc[2][0] = fmx2(a2, b0, acc[2][0]); acc[2][1] = fmx2(a2, b1, acc[2][1]);
                acc[3][0] = fmx2(a3, b0, acc[3][0]); acc[3][1] = fmx2(a3, b1, acc[3][1]);
            }
            __syncthreads();
        }
        #pragma unroll
        for (int a = 0; a < 4; a++) {
            float2 lo = upk2(acc[a][0]), hi = upk2(acc[a][1]);
            float4 v = make_float4(lo.x, lo.y, hi.x, hi.y);
            int gi = i0 + ty * 4 + a;
            *(float4*)(G + gi * BDIM + j0 + tx * 4) = v;
            int c = gi - (j0 + tx * 4);
            if (c >= 0 && c < 4) d_dg[kz][z][gi] = (&v.x)[c];
        }
    } else if (bid == 295 && wid == 0) {
        // label width detect: int64 labels < 512 -> every odd int32 word is 0
        int hi = 0;
        #pragma unroll
        for (int k = 0; k < 6; k++) hi |= lab32[2 * (lane + 32 * k) + 1];
        unsigned any = __ballot_sync(0xffffffffu, hi != 0);
        if (lane == 0) d_labmode = any ? 0 : 1;
    }

    gridbar(NBLK);  // ---- barrier 1 ----

    // ========== Phase 2: combine G, invD, diag, sum(D) + CE ==========
    {
        // stage combined sq norms into shared (every block)
        for (int i = t; i < 2 * BDIM; i += 256) {
            int z = i >= BDIM;
            int r = i - (z ? BDIM : 0);
            s_sq[i] = (d_dg[0][z][r] + d_dg[1][z][r]) + (d_dg[2][z][r] + d_dg[3][z][r]);
        }
        __syncthreads();

        // CE: warp-per-row (first 48 blocks' warps)
        const int gw = bid * 8 + wid;
        if (gw < BDIM) {
            const float* __restrict__ x = fs + gw * CDIM;
            float4 v[4];
            #pragma unroll
            for (int k = 0; k < 4; k++)
                v[k] = *(const float4*)(x + lane * 4 + 128 * k);
            float m = fmaxf(fmaxf(fmaxf(v[0].x, v[0].y), fmaxf(v[0].z, v[0].w)),
                            fmaxf(fmaxf(v[1].x, v[1].y), fmaxf(v[1].z, v[1].w)));
            m = fmaxf(m, fmaxf(fmaxf(fmaxf(v[2].x, v[2].y), fmaxf(v[2].z, v[2].w)),
                               fmaxf(fmaxf(v[3].x, v[3].y), fmaxf(v[3].z, v[3].w))));
            #pragma unroll
            for (int o = 16; o; o >>= 1) m = fmaxf(m, __shfl_xor_sync(0xffffffffu, m, o));
            float s = 0.f;
            #pragma unroll
            for (int k = 0; k < 4; k++)
                s += expf(v[k].x - m) + expf(v[k].y - m) + expf(v[k].z - m) + expf(v[k].w - m);
            #pragma unroll
            for (int o = 16; o; o >>= 1) s += __shfl_xor_sync(0xffffffffu, s, o);
            if (lane == 0) {
                int L = lab32[d_labmode ? 2 * gw : gw];
                d_cep[gw] = (logf(s) + m) - x[L];
            }
        }

        float dz0 = 0.f, dz1 = 0.f;
        for (int e = bid * 256 + t; e < 2 * B2; e += NBLK * 256) {
            int z = (e >= B2);
            int ee = e - (z ? B2 : 0);
            int i = ee / BDIM;
            int j = ee - i * BDIM;
            float g = (d_Gbig[z * B2 + ee] + d_Gbig[(2 + z) * B2 + ee])
                    + (d_Gbig[(4 + z) * B2 + ee] + d_Gbig[(6 + z) * B2 + ee]);
            d_Gbig[z * B2 + ee] = g;   // combined G in kz=0 slot (same thread RW)
            float* __restrict__ iD = z ? d_iDt : d_iDs;
            if (i == j) {
                iD[ee] = 0.f;
            } else {
                float si = s_sq[z * BDIM + i];
                float sj = s_sq[z * BDIM + j];
                float d = sqrtf(fmaxf(si + sj - 2.f * g, 1e-12f));
                iD[ee] = 1.f / d;
                if (z) dz1 += d; else dz0 += d;
            }
        }
        dz0 = block_reduce_256(dz0, sred);
        if (t == 0) d_dsum[bid] = dz0;
        dz1 = block_reduce_256(dz1, sred);
        if (t == 0) d_dsum[NBLK + bid] = dz1;
    }

    gridbar(2 * NBLK);  // ---- barrier 2 ----

    // ========== Phase 3: angle smooth-L1 (f32x2) + dist smooth-L1 ==========
    {   // every block reduces the Σd partials (identical fixed order)
        float ps  = d_dsum[t]        + ((t < NBLK - 256) ? d_dsum[t + 256] : 0.f);
        float pt2 = d_dsum[NBLK + t] + ((t < NBLK - 256) ? d_dsum[NBLK + t + 256] : 0.f);
        ps = block_reduce_256(ps, sred);
        if (t == 0) ssum[0] = ps;
        pt2 = block_reduce_256(pt2, sred);
        if (t == 0) ssum[1] = pt2;
        __syncthreads();
    }

    if (bid < 294) {
        const float* __restrict__ GS = d_Gbig;         // combined G (s)
        const float* __restrict__ GT = d_Gbig + B2;    // combined G (t)
        const float ims = 147072.f / ssum[0];
        const float imt = 147072.f / ssum[1];
        const int bx = bid % 21, by = bid / 21;        // by 0..13
        int rem = bx, ti = 0;
        while (rem >= 6 - ti) { rem -= 6 - ti; ti++; }
        const int tj = ti + rem;
        const int tx = t & 15, ty = t >> 4;
        const int i0 = ti * 64 + ty * 4;
        const int j0 = tj * 64 + tx * 4;

        // ---- dist slice (1/294 of B^2) ----
        float dacc = 0.f;
        {
            int e0 = (int)(((long long)bid * B2) / 294);
            int e1 = (int)(((long long)(bid + 1) * B2) / 294);
            for (int e = e0 + t; e < e1; e += 256) {
                int i = e / BDIM;
                int j = e - i * BDIM;
                float dS = 0.f, dT = 0.f;
                if (i != j) {
                    float gS = GS[e], gT = GT[e];
                    dS = sqrtf(fmaxf(s_sq[i] + s_sq[j] - 2.f * gS, 1e-12f));
                    dT = sqrtf(fmaxf(s_sq[BDIM + i] + s_sq[BDIM + j] - 2.f * gT, 1e-12f));
                }
                float a = fabsf(dS * ims - dT * imt);
                float mm = fminf(a, 1.f);
                dacc = fmaf(mm, fmaf(-0.5f, mm, a), dacc);
            }
        }

        // ---- angle tile: preload G tiles as packed u64 pairs ----
        u64 g2S[4][2], g2T[4][2];
        #pragma unroll
        for (int a = 0; a < 4; a++) {
            const u64* ps_ = (const u64*)(GS + (i0 + a) * BDIM + j0);
            g2S[a][0] = ps_[0]; g2S[a][1] = ps_[1];
            const u64* pt_ = (const u64*)(GT + (i0 + a) * BDIM + j0);
            g2T[a][0] = pt_[0]; g2T[a][1] = pt_[1];
        }
        const u64 M1 = pk2(-1.f, -1.f);
        const int b0 = (by * BDIM) / 14;
        const int b1 = ((by + 1) * BDIM) / 14;

        float acc0 = 0.f, acc1 = 0.f, acc2 = 0.f, acc3 = 0.f;
        for (int b = b0; b < b1; b++) {
            const int ro = b * BDIM;
            // j-side operands: memory layout == packed layout -> direct u64 loads
            const u64* pgjS = (const u64*)(GS + ro + j0);
            const u64* pujS = (const u64*)(d_iDs + ro + j0);
            const u64* pgjT = (const u64*)(GT + ro + j0);
            const u64* pujT = (const u64*)(d_iDt + ro + j0);
            u64 gbj2S[2] = { pgjS[0], pgjS[1] };
            u64 uj2S[2]  = { pujS[0], pujS[1] };
            u64 gbj2T[2] = { pgjT[0], pgjT[1] };
            u64 uj2T[2]  = { pujT[0], pujT[1] };
            // i-side scalars (need broadcast duplication)
            float4 gbiS = *(const float4*)(GS + ro + i0);
            float4 ibiS = *(const float4*)(d_iDs + ro + i0);
            float4 gbiT = *(const float4*)(GT + ro + i0);
            float4 ibiT = *(const float4*)(d_iDt + ro + i0);
            float sqS = s_sq[b], sqT = s_sq[BDIM + b];

            u64 si2S[4], si2T[4], uu2S[4][2], uu2T[4][2];
            {
                float s0 = sqS - gbiS.x, s1 = sqS - gbiS.y, s2 = sqS - gbiS.z, s3 = sqS - gbiS.w;
                si2S[0] = pk2(s0, s0); si2S[1] = pk2(s1, s1);
                si2S[2] = pk2(s2, s2); si2S[3] = pk2(s3, s3);
                float t0 = sqT - gbiT.x, t1 = sqT - gbiT.y, t2 = sqT - gbiT.z, t3 = sqT - gbiT.w;
                si2T[0] = pk2(t0, t0); si2T[1] = pk2(t1, t1);
                si2T[2] = pk2(t2, t2); si2T[3] = pk2(t3, t3);
                u64 uiS[4] = { pk2(ibiS.x, ibiS.x), pk2(ibiS.y, ibiS.y),
                               pk2(ibiS.z, ibiS.z), pk2(ibiS.w, ibiS.w) };
                u64 uiT[4] = { pk2(ibiT.x, ibiT.x), pk2(ibiT.y, ibiT.y),
                               pk2(ibiT.z, ibiT.z), pk2(ibiT.w, ibiT.w) };
                #pragma unroll
                for (int a = 0; a < 4; a++) {
                    uu2S[a][0] = mulx2(uiS[a], uj2S[0]); uu2S[a][1] = mulx2(uiS[a], uj2S[1]);
                    uu2T[a][0] = mulx2(uiT[a], uj2T[0]); uu2T[a][1] = mulx2(uiT[a], uj2T[1]);
                }
            }

            #pragma unroll
            for (int a = 0; a < 4; a++) {
                float la = 0.f;
                #pragma unroll
                for (int p = 0; p < 2; p++) {
                    u64 wS = fmx2(gbj2S[p], M1, si2S[a]);          // si - gbj
                    u64 vS = mulx2(addx2(g2S[a][p], wS), uu2S[a][p]);
                    u64 wT = fmx2(gbj2T[p], M1, si2T[a]);
                    u64 vT = mulx2(addx2(g2T[a][p], wT), uu2T[a][p]);
                    float2 d = upk2(fmx2(vT, M1, vS));             // vs - vt
                    float a0 = fabsf(d.x), m0 = fminf(a0, 1.f);
                    la = fmaf(m0, fmaf(-0.5f, m0, a0), la);
                    float a1 = fabsf(d.y), m1 = fminf(a1, 1.f);
                    la = fmaf(m1, fmaf(-0.5f, m1, a1), la);
                }
                if (a == 0) acc0 += la; else if (a == 1) acc1 += la;
                else if (a == 2) acc2 += la; else acc3 += la;
            }
        }
        float aacc = (acc0 + acc1) + (acc2 + acc3);
        if (ti != tj) aacc *= 2.f;

        aacc = block_reduce_256(aacc, sred);
        if (t == 0) d_angp[bid] = aacc;
        dacc = block_reduce_256(dacc, sred);
        if (t == 0) d_distp[bid] = dacc;
    }

    gridbar(3 * NBLK);  // ---- barrier 3 ----

    // ========== Phase 4: finalize (block 0) ==========
    if (bid == 0) {
        __shared__ double dsh[8];
        double ce = (double)d_cep[t] + ((t < BDIM - 256) ? (double)d_cep[t + 256] : 0.0);
        double di = 0.0, an = 0.0;
        if (t < 294) { di = (double)d_distp[t]; an = (double)d_angp[t]; }
        if (t < 38)  { di += (double)d_distp[t + 256]; an += (double)d_angp[t + 256]; }
        #pragma unroll
        for (int o = 16; o; o >>= 1) {
            ce += __shfl_xor_sync(0xffffffffu, ce, o);
            di += __shfl_xor_sync(0xffffffffu, di, o);
            an += __shfl_xor_sync(0xffffffffu, an, o);
        }
        if (lane == 0) dsh[wid] = ce;
        __syncthreads();
        if (t == 0) { for (int i = 1; i < 8; i++) ce += dsh[i]; }
        __syncthreads();
        if (lane == 0) dsh[wid] = di;
        __syncthreads();
        if (t == 0) { for (int i = 1; i < 8; i++) di += dsh[i]; }
        __syncthreads();
        if (lane == 0) dsh[wid] = an;
        __syncthreads();
        if (t == 0) { for (int i = 1; i < 8; i++) an += dsh[i]; }
        __syncthreads();

        for (int i = t; i < nout; i += 256) out[i] = 0.f;
        if (t == 0) {
            double tot = ce / (double)BDIM
                       + di / (double)B2
                       + an / ((double)BDIM * (double)B2);
            out[0] = (float)tot;
        }
    }
}

// ================= launch =================
extern "C" void kernel_launch(void* const* d_in, const int* in_sizes, int n_in,
                              void* d_out, int out_size) {
    const float* fs = (const float*)d_in[0];
    const float* ft = (const float*)d_in[1];
    const int* lb = (const int*)d_in[2];
    float* out = (float*)d_out;

    kInit<<<1, 1>>>();
    kMain<<<NBLK, 256>>>(fs, ft, lb, out, out_size);
}

// round 7
// speedup vs baseline: 1.4271x; 1.0592x over previous
#include <cuda_runtime.h>

typedef unsigned long long u64;
#define BDIM 384
#define CDIM 512
#define B2   147456          // 384*384
#define NBLK 296             // 2 CTAs per SM * 148 SMs

// ---------------- scratch (no allocations allowed) ----------------
// G partials: slot (kz*2+z); kz=0 slots become the combined G after phase 2.
__device__ __align__(16) float d_Gbig[8 * B2];
__device__ __align__(16) float d_iD[2 * B2];       // [z][B2]
__device__ __align__(16) float d_dg[4][2][BDIM];   // diag partials [kz][z][i]
__device__ __align__(16) float d_dsum[2 * NBLK];   // pdist partial sums [z][blk]
__device__ __align__(16) float d_cep[BDIM];        // CE per-row loss
__device__ __align__(16) float d_distp[NBLK];
__device__ __align__(16) float d_angp[NBLK];
__device__ unsigned d_barcnt = 0;                  // reset by block 0 at kernel end
__device__ int d_labmode;                          // 1 = labels int64, 0 = int32

// ---------------- f32x2 packed helpers ----------------
__device__ __forceinline__ u64 pk2(float lo, float hi) {
    u64 r; asm("mov.b64 %0,{%1,%2};" : "=l"(r) : "f"(lo), "f"(hi)); return r;
}
__device__ __forceinline__ float2 upk2(u64 v) {
    float2 f; asm("mov.b64 {%0,%1},%2;" : "=f"(f.x), "=f"(f.y) : "l"(v)); return f;
}
__device__ __forceinline__ u64 addx2(u64 a, u64 b) {
    u64 r; asm("add.rn.f32x2 %0,%1,%2;" : "=l"(r) : "l"(a), "l"(b)); return r;
}
__device__ __forceinline__ u64 mulx2(u64 a, u64 b) {
    u64 r; asm("mul.rn.f32x2 %0,%1,%2;" : "=l"(r) : "l"(a), "l"(b)); return r;
}
__device__ __forceinline__ u64 fmx2(u64 a, u64 b, u64 c) {
    u64 r; asm("fma.rn.f32x2 %0,%1,%2,%3;" : "=l"(r) : "l"(a), "l"(b), "l"(c)); return r;
}

__device__ __forceinline__ float block_reduce_256(float v, float* sh8) {
    #pragma unroll
    for (int o = 16; o; o >>= 1) v += __shfl_xor_sync(0xffffffffu, v, o);
    int lane = threadIdx.x & 31, w = threadIdx.x >> 5;
    if (lane == 0) sh8[w] = v;
    __syncthreads();
    v = (threadIdx.x < 8) ? sh8[threadIdx.x] : 0.f;
    if (w == 0) {
        #pragma unroll
        for (int o = 4; o; o >>= 1) v += __shfl_xor_sync(0xffffffffu, v, o);
    }
    __syncthreads();
    return v;  // valid on thread 0
}

// full barrier: arrive + wait
__device__ __forceinline__ void gridbar(unsigned target) {
    __syncthreads();
    if (threadIdx.x == 0) {
        __threadfence();
        atomicAdd(&d_barcnt, 1u);
        unsigned v;
        do {
            asm volatile("ld.acquire.gpu.u32 %0,[%1];" : "=r"(v) : "l"(&d_barcnt));
        } while (v < target);
    }
    __syncthreads();
}
// arrive-only (for blocks that exit afterwards)
__device__ __forceinline__ void gridbar_arrive() {
    __syncthreads();
    if (threadIdx.x == 0) {
        __threadfence();
        atomicAdd(&d_barcnt, 1u);
    }
}

// ================= THE persistent kernel =================
__global__ void __launch_bounds__(256, 2) kMain(const float* __restrict__ fs,
                                                const float* __restrict__ ft,
                                                const int* __restrict__ lab32,
                                                float* __restrict__ out, int nout) {
    // smem union: phase1 GEMM tiles (24KB) / phase3 angle staging (16KB)
    __shared__ __align__(16) char sh_raw[24576];
    u64   (*sA2)[64] = (u64 (*)[64])sh_raw;                 // [32][64] u64 = 16KB
    float (*sB)[64]  = (float (*)[64])(sh_raw + 16384);     // [32][64] f32 = 8KB
    float* sAng      = (float*)sh_raw;                      // [2][4][8][64] = 16KB
    __shared__ float s_sq[2 * BDIM];
    __shared__ float sred[9];
    __shared__ float ssum[2];
    const int bid = blockIdx.x;
    const int t = threadIdx.x;
    const int lane = t & 31, wid = t >> 5;

    // ========== Phase 1: GEMM (K-split 4, f32x2, reg-prefetch), 288 jobs ==========
    if (bid < 288) {
        const int tile = bid % 36;
        const int zz = bid / 36;          // 0..7
        const int z = zz & 1, kz = zz >> 1;
        const float* __restrict__ F = z ? ft : fs;
        float* __restrict__ G = d_Gbig + (kz * 2 + z) * B2;
        const int i0 = (tile / 6) * 64, j0 = (tile % 6) * 64;
        const int kbase = kz * 128;
        const int tx = t & 15, ty = t >> 4;
        const int lr = t & 63, lk = (t >> 6) * 8;

        const float* srcA = F + (i0 + lr) * CDIM + kbase + lk;
        const float* srcB = F + (j0 + lr) * CDIM + kbase + lk;
        float4 va0, va1, vb0, vb1;
        va0 = *(const float4*)srcA;  va1 = *(const float4*)(srcA + 4);
        vb0 = *(const float4*)srcB;  vb1 = *(const float4*)(srcB + 4);

        u64 acc[4][2] = {};
        #pragma unroll
        for (int c = 0; c < 4; c++) {
            sA2[lk + 0][lr] = pk2(va0.x, va0.x); sA2[lk + 1][lr] = pk2(va0.y, va0.y);
            sA2[lk + 2][lr] = pk2(va0.z, va0.z); sA2[lk + 3][lr] = pk2(va0.w, va0.w);
            sA2[lk + 4][lr] = pk2(va1.x, va1.x); sA2[lk + 5][lr] = pk2(va1.y, va1.y);
            sA2[lk + 6][lr] = pk2(va1.z, va1.z); sA2[lk + 7][lr] = pk2(va1.w, va1.w);
            sB[lk + 0][lr] = vb0.x; sB[lk + 1][lr] = vb0.y;
            sB[lk + 2][lr] = vb0.z; sB[lk + 3][lr] = vb0.w;
            sB[lk + 4][lr] = vb1.x; sB[lk + 5][lr] = vb1.y;
            sB[lk + 6][lr] = vb1.z; sB[lk + 7][lr] = vb1.w;
            __syncthreads();
            if (c < 3) {   // prefetch next chunk while computing this one
                const float* pa = srcA + (c + 1) * 32;
                const float* pb = srcB + (c + 1) * 32;
                va0 = *(const float4*)pa;  va1 = *(const float4*)(pa + 4);
                vb0 = *(const float4*)pb;  vb1 = *(const float4*)(pb + 4);
            }
            #pragma unroll 8
            for (int kk = 0; kk < 32; kk++) {
                u64 a0 = sA2[kk][ty * 4 + 0], a1 = sA2[kk][ty * 4 + 1];
                u64 a2 = sA2[kk][ty * 4 + 2], a3 = sA2[kk][ty * 4 + 3];
                const u64* bp = (const u64*)&sB[kk][tx * 4];
                u64 b0 = bp[0], b1 = bp[1];
                acc[0][0] = fmx2(a0, b0, acc[0][0]); acc[0][1] = fmx2(a0, b1, acc[0][1]);
                acc[1][0] = fmx2(a1, b0, acc[1][0]); acc[1][1] = fmx2(a1, b1, acc[1][1]);
                acc[2][0] = fmx2(a2, b0, acc[2][0]); acc[2][1] = fmx2(a2, b1, acc[2][1]);
                acc[3][0] = fmx2(a3, b0, acc[3][0]); acc[3][1] = fmx2(a3, b1, acc[3][1]);
            }
            __syncthreads();
        }
        #pragma unroll
        for (int a = 0; a < 4; a++) {
            float2 lo = upk2(acc[a][0]), hi = upk2(acc[a][1]);
            float4 v = make_float4(lo.x, lo.y, hi.x, hi.y);
            int gi = i0 + ty * 4 + a;
            *(float4*)(G + gi * BDIM + j0 + tx * 4) = v;
            int c = gi - (j0 + tx * 4);
            if (c >= 0 && c < 4) d_dg[kz][z][gi] = (&v.x)[c];
        }
    } else if (bid == 295 && wid == 0) {
        // label width detect: int64 labels < 512 -> every odd int32 word is 0
        int hi = 0;
        #pragma unroll
        for (int k = 0; k < 6; k++) hi |= lab32[2 * (lane + 32 * k) + 1];
        unsigned any = __ballot_sync(0xffffffffu, hi != 0);
        if (lane == 0) d_labmode = any ? 0 : 1;
    }

    gridbar(NBLK);  // ---- barrier 1 ----

    // ========== Phase 2: combine G, invD, diag, sum(D) + CE ==========
    {
        for (int i = t; i < 2 * BDIM; i += 256) {
            int z = i >= BDIM;
            int r = i - (z ? BDIM : 0);
            s_sq[i] = (d_dg[0][z][r] + d_dg[1][z][r]) + (d_dg[2][z][r] + d_dg[3][z][r]);
        }
        __syncthreads();

        const int gw = bid * 8 + wid;
        if (gw < BDIM) {
            const float* __restrict__ x = fs + gw * CDIM;
            float4 v[4];
            #pragma unroll
            for (int k = 0; k < 4; k++)
                v[k] = *(const float4*)(x + lane * 4 + 128 * k);
            float m = fmaxf(fmaxf(fmaxf(v[0].x, v[0].y), fmaxf(v[0].z, v[0].w)),
                            fmaxf(fmaxf(v[1].x, v[1].y), fmaxf(v[1].z, v[1].w)));
            m = fmaxf(m, fmaxf(fmaxf(fmaxf(v[2].x, v[2].y), fmaxf(v[2].z, v[2].w)),
                               fmaxf(fmaxf(v[3].x, v[3].y), fmaxf(v[3].z, v[3].w))));
            #pragma unroll
            for (int o = 16; o; o >>= 1) m = fmaxf(m, __shfl_xor_sync(0xffffffffu, m, o));
            float s = 0.f;
            #pragma unroll
            for (int k = 0; k < 4; k++)
                s += expf(v[k].x - m) + expf(v[k].y - m) + expf(v[k].z - m) + expf(v[k].w - m);
            #pragma unroll
            for (int o = 16; o; o >>= 1) s += __shfl_xor_sync(0xffffffffu, s, o);
            if (lane == 0) {
                int L = lab32[d_labmode ? 2 * gw : gw];
                d_cep[gw] = (logf(s) + m) - x[L];
            }
        }

        float dz0 = 0.f, dz1 = 0.f;
        for (int e = bid * 256 + t; e < 2 * B2; e += NBLK * 256) {
            int z = (e >= B2);
            int ee = e - (z ? B2 : 0);
            int i = ee / BDIM;
            int j = ee - i * BDIM;
            float g = (d_Gbig[z * B2 + ee] + d_Gbig[(2 + z) * B2 + ee])
                    + (d_Gbig[(4 + z) * B2 + ee] + d_Gbig[(6 + z) * B2 + ee]);
            d_Gbig[z * B2 + ee] = g;   // combined G in kz=0 slot
            if (i == j) {
                d_iD[z * B2 + ee] = 0.f;
            } else {
                float si = s_sq[z * BDIM + i];
                float sj = s_sq[z * BDIM + j];
                float d = sqrtf(fmaxf(si + sj - 2.f * g, 1e-12f));
                d_iD[z * B2 + ee] = 1.f / d;
                if (z) dz1 += d; else dz0 += d;
            }
        }
        dz0 = block_reduce_256(dz0, sred);
        if (t == 0) d_dsum[bid] = dz0;
        dz1 = block_reduce_256(dz1, sred);
        if (t == 0) d_dsum[NBLK + bid] = dz1;
    }

    gridbar(2 * NBLK);  // ---- barrier 2 ----

    // ========== Phase 3: angle smooth-L1 (f32x2, smem-staged) + dist smooth-L1 ==========
    {   // every block reduces the Σd partials (identical fixed order)
        float ps  = d_dsum[t]        + ((t < NBLK - 256) ? d_dsum[t + 256] : 0.f);
        float pt2 = d_dsum[NBLK + t] + ((t < NBLK - 256) ? d_dsum[NBLK + t + 256] : 0.f);
        ps = block_reduce_256(ps, sred);
        if (t == 0) ssum[0] = ps;
        pt2 = block_reduce_256(pt2, sred);
        if (t == 0) ssum[1] = pt2;
        __syncthreads();
    }

    if (bid < 294) {
        const float* __restrict__ GS = d_Gbig;         // combined G (s)
        const float* __restrict__ GT = d_Gbig + B2;    // combined G (t)
        const float ims = 147072.f / ssum[0];
        const float imt = 147072.f / ssum[1];
        const int bx = bid % 21, by = bid / 21;        // by 0..13
        int rem = bx, ti = 0;
        while (rem >= 6 - ti) { rem -= 6 - ti; ti++; }
        const int tj = ti + rem;
        const int tx = t & 15, ty = t >> 4;
        const int i0t = ti * 64, j0t = tj * 64;
        const int i0 = i0t + ty * 4;
        const int j0 = j0t + tx * 4;

        // ---- dist slice (1/294 of B^2) ----
        float dacc = 0.f;
        {
            int e0 = (int)(((long long)bid * B2) / 294);
            int e1 = (int)(((long long)(bid + 1) * B2) / 294);
            for (int e = e0 + t; e < e1; e += 256) {
                int i = e / BDIM;
                int j = e - i * BDIM;
                float dS = 0.f, dT = 0.f;
                if (i != j) {
                    float gS = GS[e], gT = GT[e];
                    dS = sqrtf(fmaxf(s_sq[i] + s_sq[j] - 2.f * gS, 1e-12f));
                    dT = sqrtf(fmaxf(s_sq[BDIM + i] + s_sq[BDIM + j] - 2.f * gT, 1e-12f));
                }
                float a = fabsf(dS * ims - dT * imt);
                float mm = fminf(a, 1.f);
                dacc = fmaf(mm, fmaf(-0.5f, mm, a), dacc);
            }
        }

        // ---- angle tile: preload G tiles as packed u64 pairs (regs, once) ----
        u64 g2S[4][2], g2T[4][2];
        #pragma unroll
        for (int a = 0; a < 4; a++) {
            const u64* ps_ = (const u64*)(GS + (i0 + a) * BDIM + j0);
            g2S[a][0] = ps_[0]; g2S[a][1] = ps_[1];
            const u64* pt_ = (const u64*)(GT + (i0 + a) * BDIM + j0);
            g2T[a][0] = pt_[0]; g2T[a][1] = pt_[1];
        }
        const u64 M1 = pk2(-1.f, -1.f);
        const int b0 = (by * BDIM) / 14;
        const int b1 = ((by + 1) * BDIM) / 14;
        const int nb = b1 - b0;
        const int nch = (nb + 3) >> 2;

        // staging loader: chunk c -> 2 float4 per thread
        // arr bits: bit0=z(S/T), bit1=(G vs iD), bit2=(i vs j)
        const int g0 = t, g1 = t + 256;
        const int bl_0 = g0 >> 7, ar_0 = (g0 & 127) >> 4, f4_0 = (g0 & 15) * 4;
        const int bl_1 = g1 >> 7, ar_1 = (g1 & 127) >> 4, f4_1 = (g1 & 15) * 4;
        const float* base_0 = ((ar_0 & 2) ? d_iD : d_Gbig) + (ar_0 & 1) * B2
                              + ((ar_0 & 4) ? j0t : i0t) + f4_0;
        const float* base_1 = ((ar_1 & 2) ? d_iD : d_Gbig) + (ar_1 & 1) * B2
                              + ((ar_1 & 4) ? j0t : i0t) + f4_1;
        const int so_0 = (bl_0 * 8 + ar_0) * 64 + f4_0;
        const int so_1 = (bl_1 * 8 + ar_1) * 64 + f4_1;

        float4 vr0, vr1;
        {
            int bb0 = b0 + bl_0; if (bb0 > 383) bb0 = 383;
            int bb1 = b0 + bl_1; if (bb1 > 383) bb1 = 383;
            vr0 = *(const float4*)(base_0 + bb0 * BDIM);
            vr1 = *(const float4*)(base_1 + bb1 * BDIM);
        }

        float acc0 = 0.f, acc1 = 0.f, acc2 = 0.f, acc3 = 0.f;
        int buf = 0;
        for (int c = 0; c < nch; c++) {
            *(float4*)(sAng + buf * 2048 + so_0) = vr0;
            *(float4*)(sAng + buf * 2048 + so_1) = vr1;
            __syncthreads();
            if (c + 1 < nch) {
                int bb0 = b0 + (c + 1) * 4 + bl_0; if (bb0 > 383) bb0 = 383;
                int bb1 = b0 + (c + 1) * 4 + bl_1; if (bb1 > 383) bb1 = 383;
                vr0 = *(const float4*)(base_0 + bb0 * BDIM);
                vr1 = *(const float4*)(base_1 + bb1 * BDIM);
            }
            const int cnt = min(4, nb - c * 4);
            for (int bl = 0; bl < cnt; bl++) {
                const int b = b0 + c * 4 + bl;
                const float* sl = sAng + buf * 2048 + bl * 512;
                float4 gbiS = *(const float4*)(sl + ty * 4);
                float4 gbiT = *(const float4*)(sl + 64 + ty * 4);
                float4 ibiS = *(const float4*)(sl + 128 + ty * 4);
                float4 ibiT = *(const float4*)(sl + 192 + ty * 4);
                const u64* pgjS = (const u64*)(sl + 256 + tx * 4);
                const u64* pgjT = (const u64*)(sl + 320 + tx * 4);
                const u64* pujS = (const u64*)(sl + 384 + tx * 4);
                const u64* pujT = (const u64*)(sl + 448 + tx * 4);
                u64 gbj2S[2] = { pgjS[0], pgjS[1] };
                u64 gbj2T[2] = { pgjT[0], pgjT[1] };
                u64 uj2S[2]  = { pujS[0], pujS[1] };
                u64 uj2T[2]  = { pujT[0], pujT[1] };
                float sqS = s_sq[b], sqT = s_sq[BDIM + b];

                u64 si2S[4], si2T[4], uu2S[4][2], uu2T[4][2];
                {
                    float s0 = sqS - gbiS.x, s1 = sqS - gbiS.y;
                    float s2 = sqS - gbiS.z, s3 = sqS - gbiS.w;
                    si2S[0] = pk2(s0, s0); si2S[1] = pk2(s1, s1);
                    si2S[2] = pk2(s2, s2); si2S[3] = pk2(s3, s3);
                    float t0 = sqT - gbiT.x, t1 = sqT - gbiT.y;
                    float t2 = sqT - gbiT.z, t3 = sqT - gbiT.w;
                    si2T[0] = pk2(t0, t0); si2T[1] = pk2(t1, t1);
                    si2T[2] = pk2(t2, t2); si2T[3] = pk2(t3, t3);
                    u64 uiS[4] = { pk2(ibiS.x, ibiS.x), pk2(ibiS.y, ibiS.y),
                                   pk2(ibiS.z, ibiS.z), pk2(ibiS.w, ibiS.w) };
                    u64 uiT[4] = { pk2(ibiT.x, ibiT.x), pk2(ibiT.y, ibiT.y),
                                   pk2(ibiT.z, ibiT.z), pk2(ibiT.w, ibiT.w) };
                    #pragma unroll
                    for (int a = 0; a < 4; a++) {
                        uu2S[a][0] = mulx2(uiS[a], uj2S[0]); uu2S[a][1] = mulx2(uiS[a], uj2S[1]);
                        uu2T[a][0] = mulx2(uiT[a], uj2T[0]); uu2T[a][1] = mulx2(uiT[a], uj2T[1]);
                    }
                }

                #pragma unroll
                for (int a = 0; a < 4; a++) {
                    float la = 0.f;
                    #pragma unroll
                    for (int p = 0; p < 2; p++) {
                        u64 wS = fmx2(gbj2S[p], M1, si2S[a]);          // si - gbj
                        u64 vS = mulx2(addx2(g2S[a][p], wS), uu2S[a][p]);
                        u64 wT = fmx2(gbj2T[p], M1, si2T[a]);
                        u64 vT = mulx2(addx2(g2T[a][p], wT), uu2T[a][p]);
                        float2 d = upk2(fmx2(vT, M1, vS));             // vs - vt
                        float a0 = fabsf(d.x), m0 = fminf(a0, 1.f);
                        la = fmaf(m0, fmaf(-0.5f, m0, a0), la);
                        float a1 = fabsf(d.y), m1 = fminf(a1, 1.f);
                        la = fmaf(m1, fmaf(-0.5f, m1, a1), la);
                    }
                    if (a == 0) acc0 += la; else if (a == 1) acc1 += la;
                    else if (a == 2) acc2 += la; else acc3 += la;
                }
            }
            buf ^= 1;
        }
        float aacc = (acc0 + acc1) + (acc2 + acc3);
        if (ti != tj) aacc *= 2.f;

        aacc = block_reduce_256(aacc, sred);
        if (t == 0) d_angp[bid] = aacc;
        dacc = block_reduce_256(dacc, sred);
        if (t == 0) d_distp[bid] = dacc;
    }

    // ---- barrier 3: arrive-only for blocks != 0; block 0 waits + finalizes ----
    if (bid != 0) {
        gridbar_arrive();
        return;
    }
    gridbar(3 * NBLK);

    // ========== Phase 4: finalize (block 0) ==========
    {
        __shared__ double dsh[8];
        double ce = (double)d_cep[t] + ((t < BDIM - 256) ? (double)d_cep[t + 256] : 0.0);
        double di = 0.0, an = 0.0;
        if (t < 294) { di = (double)d_distp[t]; an = (double)d_angp[t]; }
        if (t < 38)  { di += (double)d_distp[t + 256]; an += (double)d_angp[t + 256]; }
        #pragma unroll
        for (int o = 16; o; o >>= 1) {
            ce += __shfl_xor_sync(0xffffffffu, ce, o);
            di += __shfl_xor_sync(0xffffffffu, di, o);
            an += __shfl_xor_sync(0xffffffffu, an, o);
        }
        if (lane == 0) dsh[wid] = ce;
        __syncthreads();
        if (t == 0) { for (int i = 1; i < 8; i++) ce += dsh[i]; }
        __syncthreads();
        if (lane == 0) dsh[wid] = di;
        __syncthreads();
        if (t == 0) { for (int i = 1; i < 8; i++) di += dsh[i]; }
        __syncthreads();
        if (lane == 0) dsh[wid] = an;
        __syncthreads();
        if (t == 0) { for (int i = 1; i < 8; i++) an += dsh[i]; }
        __syncthreads();

        for (int i = t; i < nout; i += 256) out[i] = 0.f;
        if (t == 0) {
            double tot = ce / (double)BDIM
                       + di / (double)B2
                       + an / ((double)BDIM * (double)B2);
            out[0] = (float)tot;
            d_barcnt = 0;   // reset for next graph replay (no other block reads it now)
        }
    }
}

// ================= launch =================
extern "C" void kernel_launch(void* const* d_in, const int* in_sizes, int n_in,
                              void* d_out, int out_size) {
    const float* fs = (const float*)d_in[0];
    const float* ft = (const float*)d_in[1];
    const int* lb = (const int*)d_in[2];
    float* out = (float*)d_out;

    kMain<<<NBLK, 256>>>(fs, ft, lb, out, out_size);
}